// round 12
// baseline (speedup 1.0000x reference)
#include <cuda_runtime.h>
#include <cuda_fp16.h>
#include <math.h>
#include <cstdint>

#define NN 4096
#define FF 128
#define DD 64
#define KH 3
#define SPLIT 3
#define KCHUNK 32
#define NCHTOT (NN / KCHUNK)    // 128
#define CHSPL 43                // chunks per split (last gets 42)

// ---------------- scratch (device globals; no allocations allowed) ----------
__device__ float g_E[NN * DD];                 // X @ W_emb
__device__ float g_XW[KH * NN * DD];           // per-hop projections
__device__ __align__(16) __half g_Ah[(size_t)KH * NN * NN]; // A in fp16 (from deg)
__device__ __align__(16) __half g_Yh[KH * DD * NN];  // (d.*XW)^T fp16
__device__ float g_Cp[SPLIT * KH * NN * DD];   // partial C per K-split
__device__ float g_dinv[KH * NN];              // deg^{-1/2}
__device__ float g_S[DD];                      // colsum(E)
__device__ float g_M[KH * DD * DD];            // M_k = E^T @ Y_k

// ---------------- helpers ----------------------------------------------------
__device__ __forceinline__ uint32_t smem_u32(const void* p) {
    uint32_t a;
    asm("{ .reg .u64 t; cvta.to.shared.u64 t, %1; cvt.u32.u64 %0, t; }" : "=r"(a) : "l"(p));
    return a;
}
#define CP_ASYNC16(dst, src) \
    asm volatile("cp.async.cg.shared.global [%0], [%1], 16;" :: "r"(dst), "l"(src) : "memory")
#define CP_COMMIT() asm volatile("cp.async.commit_group;" ::: "memory")
#define CP_WAIT(n)  asm volatile("cp.async.wait_group %0;" :: "n"(n) : "memory")

// pack two floats (x = even-k -> low half, y = odd-k -> high half) into fp16x2
__device__ __forceinline__ uint32_t f16x2(float x, float y) {
    uint32_t w;
    asm("cvt.rn.f16x2.f32 %0, %1, %2;" : "=r"(w) : "f"(y), "f"(x));
    return w;
}

__device__ __forceinline__ void mma_f16(float* d, const uint32_t* a, const uint32_t* b) {
    asm volatile(
        "mma.sync.aligned.m16n8k16.row.col.f32.f16.f16.f32 "
        "{%0,%1,%2,%3}, {%4,%5,%6,%7}, {%8,%9}, {%0,%1,%2,%3};\n"
        : "+f"(d[0]), "+f"(d[1]), "+f"(d[2]), "+f"(d[3])
        : "r"(a[0]), "r"(a[1]), "r"(a[2]), "r"(a[3]), "r"(b[0]), "r"(b[1]));
}

// ---------------- zero the atomic accumulators ------------------------------
__global__ void zero_kernel() {
    int t = blockIdx.x * blockDim.x + threadIdx.x;
    if (t < DD) g_S[t] = 0.f;
    if (t < KH * DD * DD) g_M[t] = 0.f;
}

// ---------------- E = X @ W_emb, XW[k] = X @ W_hops[k] ----------------------
__global__ void proj_kernel(const float* __restrict__ X,
                            const float* __restrict__ Wemb,
                            const float* __restrict__ Whops) {
    __shared__ float Xs[16][FF + 1];
    const int rb = blockIdx.x;
    const int m = blockIdx.y;
    const float* W = (m == 0) ? Wemb : (Whops + (size_t)(m - 1) * FF * DD);
    float* Out = (m == 0) ? g_E : (g_XW + (size_t)(m - 1) * NN * DD);
    const int t = threadIdx.x;

    #pragma unroll
    for (int i = 0; i < 2; i++) {
        int idx = t + 256 * i;
        int row = idx >> 5;
        int c4 = idx & 31;
        float4 v = *reinterpret_cast<const float4*>(X + (size_t)(rb * 16 + row) * FF + c4 * 4);
        Xs[row][c4 * 4 + 0] = v.x; Xs[row][c4 * 4 + 1] = v.y;
        Xs[row][c4 * 4 + 2] = v.z; Xs[row][c4 * 4 + 3] = v.w;
    }
    __syncthreads();

    const int c = t & 63;
    const int rq = t >> 6;
    float acc[4] = {0.f, 0.f, 0.f, 0.f};
    for (int f = 0; f < FF; f++) {
        float w = __ldg(W + (size_t)f * DD + c);
        #pragma unroll
        for (int r = 0; r < 4; r++) acc[r] += Xs[rq * 4 + r][f] * w;
    }
    #pragma unroll
    for (int r = 0; r < 4; r++)
        Out[(size_t)(rb * 16 + rq * 4 + r) * DD + c] = acc[r];
}

// ---------------- S = colsum(E). grid 32, block 256 -------------------------
__global__ void colsum_kernel() {
    __shared__ float red[4][DD];
    const int t = threadIdx.x;
    const int b = blockIdx.x;
    const int c = t & 63, g = t >> 6;
    float acc = 0.f;
    for (int r = 0; r < 32; r++)
        acc += g_E[(size_t)(b * 128 + g * 32 + r) * DD + c];
    red[g][c] = acc;
    __syncthreads();
    if (t < DD)
        atomicAdd(&g_S[t], red[0][t] + red[1][t] + red[2][t] + red[3][t]);
}

// ---------------- deg: rowsum (f32, exact) + convert A -> fp16 --------------
// dinv[k][i] = (rowsum(A_k)[i] + alpha*E[i].S)^(-1/2); Ah = fp16(A).
// grid KH*NN (one block per row), block 256.
__global__ void deg_kernel(const float* __restrict__ A,
                           const float* __restrict__ alpha_p) {
    __shared__ float wsum[8];
    __shared__ float dsum[2];
    const int bid = blockIdx.x;           // k*NN + i
    const int i = bid & (NN - 1);
    const float* Arow = A + (size_t)bid * NN;
    __half* AhRow = g_Ah + (size_t)bid * NN;
    const int t = threadIdx.x;

    float acc = 0.f;
    #pragma unroll
    for (int j = 0; j < 4; j++) {
        float4 v = *reinterpret_cast<const float4*>(Arow + (size_t)(t + 256 * j) * 4);
        acc += (v.x + v.y) + (v.z + v.w);
        uint2 w = make_uint2(f16x2(v.x, v.y), f16x2(v.z, v.w));
        *reinterpret_cast<uint2*>(AhRow + (size_t)(t + 256 * j) * 4) = w;
    }
    #pragma unroll
    for (int o = 16; o > 0; o >>= 1) acc += __shfl_down_sync(0xffffffffu, acc, o);
    if ((t & 31) == 0) wsum[t >> 5] = acc;
    __syncthreads();
    if (t < 64) {
        float p = g_E[(size_t)i * DD + t] * g_S[t];
        #pragma unroll
        for (int o = 16; o > 0; o >>= 1) p += __shfl_down_sync(0xffffffffu, p, o);
        if ((t & 31) == 0) dsum[t >> 5] = p;
    }
    __syncthreads();
    if (t == 0) {
        float rs = 0.f;
        #pragma unroll
        for (int w = 0; w < 8; w++) rs += wsum[w];
        float deg = rs + __ldg(alpha_p) * (dsum[0] + dsum[1]);
        g_dinv[bid] = 1.0f / sqrtf(deg);
    }
}

// ---------------- Yh[k][n][j] = fp16( dinv[k][j] * XW[k][j][n] ) ------------
// grid (64, KH), block 256 — 64x64 transpose tiles.
__global__ void prep_kernel() {
    __shared__ float T[64][65];
    const int k = blockIdx.y;
    const int jb = blockIdx.x * 64;
    const int t = threadIdx.x;

    #pragma unroll
    for (int q = 0; q < 4; q++) {
        int idx = t + 256 * q;            // 1024 float4
        int r = idx >> 4;
        int c4 = idx & 15;
        float dv = g_dinv[(size_t)k * NN + jb + r];
        float4 v = *reinterpret_cast<const float4*>(g_XW + ((size_t)k * NN + jb + r) * DD + c4 * 4);
        T[r][c4 * 4 + 0] = v.x * dv;
        T[r][c4 * 4 + 1] = v.y * dv;
        T[r][c4 * 4 + 2] = v.z * dv;
        T[r][c4 * 4 + 3] = v.w * dv;
    }
    __syncthreads();

    const int n = t >> 2;
    const int jq = t & 3;
    const size_t base = ((size_t)k * DD + n) * NN + jb + jq * 16;
    uint32_t w[8];
    #pragma unroll
    for (int m4 = 0; m4 < 4; m4++) {
        w[2 * m4 + 0] = f16x2(T[jq * 16 + m4 * 4 + 0][n], T[jq * 16 + m4 * 4 + 1][n]);
        w[2 * m4 + 1] = f16x2(T[jq * 16 + m4 * 4 + 2][n], T[jq * 16 + m4 * 4 + 3][n]);
    }
    *reinterpret_cast<uint4*>(g_Yh + base)     = make_uint4(w[0], w[1], w[2], w[3]);
    *reinterpret_cast<uint4*>(g_Yh + base + 8) = make_uint4(w[4], w[5], w[6], w[7]);
}

// ---------------- M_k = E^T @ (d_k . XW_k)  (64x64 each) --------------------
__global__ void mmat_kernel() {
    __shared__ float Es[64][DD];
    __shared__ float Ys[64][DD];
    const int k = blockIdx.y;
    const int base = blockIdx.x * 64;
    const int t = threadIdx.x;

    #pragma unroll
    for (int i = 0; i < 4; i++) {
        int idx = t + 256 * i;
        int row = idx >> 4;
        int c4 = idx & 15;
        float4 e = *reinterpret_cast<const float4*>(g_E + (size_t)(base + row) * DD + c4 * 4);
        *reinterpret_cast<float4*>(&Es[row][c4 * 4]) = e;
        float dv = g_dinv[(size_t)k * NN + base + row];
        float4 xw = *reinterpret_cast<const float4*>(g_XW + ((size_t)k * NN + base + row) * DD + c4 * 4);
        xw.x *= dv; xw.y *= dv; xw.z *= dv; xw.w *= dv;
        *reinterpret_cast<float4*>(&Ys[row][c4 * 4]) = xw;
    }
    __syncthreads();

    const int t1 = t >> 4, t2 = t & 15;
    float acc[4][4] = {};
    for (int j = 0; j < 64; j++) {
        float4 e = *reinterpret_cast<const float4*>(&Es[j][t1 * 4]);
        float4 y = *reinterpret_cast<const float4*>(&Ys[j][t2 * 4]);
        float ea[4] = {e.x, e.y, e.z, e.w};
        float ya[4] = {y.x, y.y, y.z, y.w};
        #pragma unroll
        for (int a = 0; a < 4; a++)
            #pragma unroll
            for (int b = 0; b < 4; b++) acc[a][b] += ea[a] * ya[b];
    }
    #pragma unroll
    for (int a = 0; a < 4; a++)
        #pragma unroll
        for (int b = 0; b < 4; b++)
            atomicAdd(&g_M[(size_t)k * DD * DD + (t1 * 4 + a) * DD + t2 * 4 + b], acc[a][b]);
}

// ---------------- C_k = A_k @ Y_k via mma.sync fp16 m16n8k16 ----------------
// grid (32, KH, 3), block 256 (8 warps, warp tile 32x32). One full wave.
// A read as PRE-CONVERTED fp16 (g_Ah) — half the fill traffic, no in-loop cvt.
// A smem: [128 rows][16 words], 16B-group rotation by (row&3) (loads 2-way).
// B smem: as round 11 (fp16, word rotation by row).
#define A_STAGE 8192                          // 128*32*2
#define B_STAGE 4096                          // 64*32*2
#define STAGE_BYTES (A_STAGE + B_STAGE)       // 12288
#define SPMM_SMEM (2 * STAGE_BYTES)           // 24576

__global__ void __launch_bounds__(256, 2) spmm_mma_kernel() {
    extern __shared__ char smem[];
    const uint32_t sb = smem_u32(smem);
    const int t = threadIdx.x;
    const int wid = t >> 5;
    const int lid = t & 31;
    const int g = lid >> 2;                // 0..7
    const int tig = lid & 3;               // 0..3
    const int warpM = wid >> 1;            // 0..3
    const int warpN = wid & 1;             // 0..1
    const int k = blockIdx.y;
    const int r0 = blockIdx.x * 128;
    const int kz = blockIdx.z;
    const int ch0 = kz * CHSPL;
    const int nch = (kz == SPLIT - 1) ? (NCHTOT - ch0) : CHSPL;  // 43/43/42
    const size_t k0 = (size_t)ch0 * KCHUNK;

    // ---- fill geometry ----
    // A: 2 x 16B per thread per chunk (fp16). 512 units = 128 rows x 4 groups.
    uint32_t adst[2];
    const __half* asrc[2];
    #pragma unroll
    for (int q = 0; q < 2; q++) {
        int idx = t + 256 * q;
        int row = idx >> 2;                // 0..127
        int c8 = idx & 3;                  // 16B group = 4 words = 8 halves
        adst[q] = (uint32_t)(row * 64 + 16 * ((c8 + (row & 3)) & 3));
        asrc[q] = g_Ah + ((size_t)k * NN + r0 + row) * NN + k0 + c8 * 8;
    }
    uint32_t bdst;
    const __half* bsrc;
    {
        int row = t >> 2;                  // 0..63
        int c4 = t & 3;                    // 16B unit = 4 words = 8 halves
        bdst = (uint32_t)(A_STAGE + row * 64 + 4 * ((4 * c4 + 4 * (row & 3)) & 15));
        bsrc = g_Yh + ((size_t)k * DD + row) * NN + k0 + c4 * 8;
    }

    float acc[2][4][4];
    #pragma unroll
    for (int mt = 0; mt < 2; mt++)
        #pragma unroll
        for (int nt = 0; nt < 4; nt++)
            #pragma unroll
            for (int r = 0; r < 4; r++) acc[mt][nt][r] = 0.f;

    // issue chunk 0
    {
        #pragma unroll
        for (int q = 0; q < 2; q++) CP_ASYNC16(sb + adst[q], asrc[q]);
        CP_ASYNC16(sb + bdst, bsrc);
        CP_COMMIT();
    }

    for (int i = 0; i < nch; i++) {
        const int st = i & 1;
        if (i + 1 < nch) {
            const uint32_t soff = sb + ((i + 1) & 1) * STAGE_BYTES;
            const int kb = (i + 1) * KCHUNK;
            #pragma unroll
            for (int q = 0; q < 2; q++) CP_ASYNC16(soff + adst[q], asrc[q] + kb);
            CP_ASYNC16(soff + bdst, bsrc + kb);
            CP_COMMIT();
            CP_WAIT(1);
        } else {
            CP_WAIT(0);
        }
        __syncthreads();

        const uint32_t* sA = reinterpret_cast<const uint32_t*>(smem + st * STAGE_BYTES);
        const uint32_t* sB = reinterpret_cast<const uint32_t*>(smem + st * STAGE_BYTES + A_STAGE);

        #pragma unroll
        for (int kb16 = 0; kb16 < 2; kb16++) {
            const int p0 = kb16 * 8;

            // A fragments: direct LDS.32 of fp16x2 (group-rotated layout)
            uint32_t af[2][4];
            const int rotA = 4 * (g & 3);
            const int wA0 = (p0 + tig + rotA) & 15;
            const int wA1 = (p0 + tig + 4 + rotA) & 15;
            #pragma unroll
            for (int mt = 0; mt < 2; mt++) {
                const int ra = warpM * 32 + mt * 16 + g;
                const int rb = ra + 8;
                af[mt][0] = sA[ra * 16 + wA0];
                af[mt][1] = sA[rb * 16 + wA0];
                af[mt][2] = sA[ra * 16 + wA1];
                af[mt][3] = sA[rb * 16 + wA1];
            }

            // B fragments: LDS.32 of fp16x2 words (rotated layout)
            uint32_t bf[4][2];
            #pragma unroll
            for (int nt = 0; nt < 4; nt++) {
                const int n_ = warpN * 32 + nt * 8 + g;
                const int rot = 4 * (n_ & 3);
                bf[nt][0] = sB[n_ * 16 + ((p0 + tig + rot) & 15)];
                bf[nt][1] = sB[n_ * 16 + ((p0 + tig + 4 + rot) & 15)];
            }

            #pragma unroll
            for (int mt = 0; mt < 2; mt++)
                #pragma unroll
                for (int nt = 0; nt < 4; nt++)
                    mma_f16(acc[mt][nt], af[mt], bf[nt]);
        }
        __syncthreads();
    }

    // ---- epilogue: write partial C ----
    float* Cb = g_Cp + ((size_t)kz * KH + k) * NN * DD + (size_t)r0 * DD;
    #pragma unroll
    for (int mt = 0; mt < 2; mt++) {
        const int row = warpM * 32 + mt * 16 + g;
        #pragma unroll
        for (int nt = 0; nt < 4; nt++) {
            const int col = warpN * 32 + nt * 8 + 2 * tig;
            *reinterpret_cast<float2*>(Cb + (size_t)row * DD + col) =
                make_float2(acc[mt][nt][0], acc[mt][nt][1]);
            *reinterpret_cast<float2*>(Cb + (size_t)(row + 8) * DD + col) =
                make_float2(acc[mt][nt][2], acc[mt][nt][3]);
        }
    }
}

// ---------------- out = relu( sum_k dinv_k[i] * (sum_z Cp + alpha*E@M_k) ) --
__global__ void final_kernel(const float* __restrict__ alpha_p,
                             float* __restrict__ out) {
    __shared__ float Ms[DD][DD];
    __shared__ float Es[4][DD];
    const int b = blockIdx.x;
    const int t = threadIdx.x;
    const int ti = t >> 6, c = t & 63;
    const int i = b * 4 + ti;
    Es[ti][c] = g_E[(size_t)i * DD + c];
    const float alpha = __ldg(alpha_p);

    float acc = 0.f;
    for (int k = 0; k < KH; k++) {
        __syncthreads();
        #pragma unroll
        for (int q = 0; q < 16; q++) {
            int idx = t + 256 * q;
            Ms[idx >> 6][idx & 63] = g_M[(size_t)k * DD * DD + idx];
        }
        __syncthreads();
        float dotm = 0.f;
        #pragma unroll 8
        for (int c1 = 0; c1 < DD; c1++) dotm += Es[ti][c1] * Ms[c1][c];
        size_t idx = ((size_t)k * NN + i) * DD + c;
        float s = alpha * dotm;
        #pragma unroll
        for (int z = 0; z < SPLIT; z++)
            s += g_Cp[(size_t)z * (KH * NN * DD) + idx];
        acc += g_dinv[(size_t)k * NN + i] * s;
    }
    out[(size_t)i * DD + c] = fmaxf(acc, 0.f);
}

// ---------------- launch ----------------------------------------------------
extern "C" void kernel_launch(void* const* d_in, const int* in_sizes, int n_in,
                              void* d_out, int out_size) {
    const float* X     = (const float*)d_in[0];
    const float* A     = (const float*)d_in[1];
    const float* Wemb  = (const float*)d_in[2];
    const float* Whops = (const float*)d_in[3];
    const float* alpha = (const float*)d_in[4];
    float* out = (float*)d_out;

    cudaFuncSetAttribute(spmm_mma_kernel,
                         cudaFuncAttributeMaxDynamicSharedMemorySize, SPMM_SMEM);

    zero_kernel<<<48, 256>>>();
    proj_kernel<<<dim3(256, 4), 256>>>(X, Wemb, Whops);
    colsum_kernel<<<32, 256>>>();
    deg_kernel<<<KH * NN, 256>>>(A, alpha);
    prep_kernel<<<dim3(64, KH), 256>>>();
    mmat_kernel<<<dim3(64, KH), 256>>>();
    spmm_mma_kernel<<<dim3(32, KH, SPLIT), 256, SPMM_SMEM>>>();
    final_kernel<<<1024, 256>>>(alpha, out);
}

// round 15
// speedup vs baseline: 1.1036x; 1.1036x over previous
#include <cuda_runtime.h>
#include <cuda_fp16.h>
#include <math.h>
#include <cstdint>

#define NN 4096
#define FF 128
#define DD 64
#define KH 3
#define SPLIT 3
#define KCHUNK 64
#define NCHTOT (NN / KCHUNK)    // 64

// ---------------- scratch (device globals; no allocations allowed) ----------
__device__ float g_E[NN * DD];                 // X @ W_emb
__device__ float g_XW[KH * NN * DD];           // per-hop projections
__device__ __align__(16) __half g_Ah[(size_t)KH * NN * NN]; // A in fp16 (from deg)
__device__ __align__(16) __half g_Yh[KH * DD * NN];  // (d.*XW)^T fp16
__device__ float g_Cp[SPLIT * KH * NN * DD];   // partial C per K-split
__device__ float g_EM[KH * NN * DD];           // alpha * E @ M_k
__device__ float g_dinv[KH * NN];              // deg^{-1/2}
__device__ float g_S[DD];                      // colsum(E)
__device__ float g_M[KH * DD * DD];            // M_k = E^T @ Y_k

// ---------------- helpers ----------------------------------------------------
__device__ __forceinline__ uint32_t smem_u32(const void* p) {
    uint32_t a;
    asm("{ .reg .u64 t; cvta.to.shared.u64 t, %1; cvt.u32.u64 %0, t; }" : "=r"(a) : "l"(p));
    return a;
}
#define CP_ASYNC16(dst, src) \
    asm volatile("cp.async.cg.shared.global [%0], [%1], 16;" :: "r"(dst), "l"(src) : "memory")
#define CP_COMMIT() asm volatile("cp.async.commit_group;" ::: "memory")
#define CP_WAIT(n)  asm volatile("cp.async.wait_group %0;" :: "n"(n) : "memory")

#define LDSM_X4(r0, r1, r2, r3, addr) \
    asm volatile("ldmatrix.sync.aligned.m8n8.x4.shared.b16 {%0,%1,%2,%3}, [%4];" \
        : "=r"(r0), "=r"(r1), "=r"(r2), "=r"(r3) : "r"(addr))

// pack two floats (x = even-k -> low half, y = odd-k -> high half) into fp16x2
__device__ __forceinline__ uint32_t f16x2(float x, float y) {
    uint32_t w;
    asm("cvt.rn.f16x2.f32 %0, %1, %2;" : "=r"(w) : "f"(y), "f"(x));
    return w;
}

__device__ __forceinline__ void mma_f16(float* d, const uint32_t* a, const uint32_t* b) {
    asm volatile(
        "mma.sync.aligned.m16n8k16.row.col.f32.f16.f16.f32 "
        "{%0,%1,%2,%3}, {%4,%5,%6,%7}, {%8,%9}, {%0,%1,%2,%3};\n"
        : "+f"(d[0]), "+f"(d[1]), "+f"(d[2]), "+f"(d[3])
        : "r"(a[0]), "r"(a[1]), "r"(a[2]), "r"(a[3]), "r"(b[0]), "r"(b[1]));
}

// ---------------- zero the atomic accumulators ------------------------------
__global__ void zero_kernel() {
    int t = blockIdx.x * blockDim.x + threadIdx.x;
    if (t < DD) g_S[t] = 0.f;
    if (t < KH * DD * DD) g_M[t] = 0.f;
}

// ---------------- E = X @ W_emb, XW[k] = X @ W_hops[k] ----------------------
__global__ void proj_kernel(const float* __restrict__ X,
                            const float* __restrict__ Wemb,
                            const float* __restrict__ Whops) {
    __shared__ float Xs[16][FF + 1];
    const int rb = blockIdx.x;
    const int m = blockIdx.y;
    const float* W = (m == 0) ? Wemb : (Whops + (size_t)(m - 1) * FF * DD);
    float* Out = (m == 0) ? g_E : (g_XW + (size_t)(m - 1) * NN * DD);
    const int t = threadIdx.x;

    #pragma unroll
    for (int i = 0; i < 2; i++) {
        int idx = t + 256 * i;
        int row = idx >> 5;
        int c4 = idx & 31;
        float4 v = *reinterpret_cast<const float4*>(X + (size_t)(rb * 16 + row) * FF + c4 * 4);
        Xs[row][c4 * 4 + 0] = v.x; Xs[row][c4 * 4 + 1] = v.y;
        Xs[row][c4 * 4 + 2] = v.z; Xs[row][c4 * 4 + 3] = v.w;
    }
    __syncthreads();

    const int c = t & 63;
    const int rq = t >> 6;
    float acc[4] = {0.f, 0.f, 0.f, 0.f};
    for (int f = 0; f < FF; f++) {
        float w = __ldg(W + (size_t)f * DD + c);
        #pragma unroll
        for (int r = 0; r < 4; r++) acc[r] += Xs[rq * 4 + r][f] * w;
    }
    #pragma unroll
    for (int r = 0; r < 4; r++)
        Out[(size_t)(rb * 16 + rq * 4 + r) * DD + c] = acc[r];
}

// ---------------- S = colsum(E). grid 32, block 256 -------------------------
__global__ void colsum_kernel() {
    __shared__ float red[4][DD];
    const int t = threadIdx.x;
    const int b = blockIdx.x;
    const int c = t & 63, g = t >> 6;
    float acc = 0.f;
    for (int r = 0; r < 32; r++)
        acc += g_E[(size_t)(b * 128 + g * 32 + r) * DD + c];
    red[g][c] = acc;
    __syncthreads();
    if (t < DD)
        atomicAdd(&g_S[t], red[0][t] + red[1][t] + red[2][t] + red[3][t]);
}

// ---------------- deg: rowsum (f32, exact) + convert A -> fp16 --------------
__global__ void deg_kernel(const float* __restrict__ A,
                           const float* __restrict__ alpha_p) {
    __shared__ float wsum[8];
    __shared__ float dsum[2];
    const int bid = blockIdx.x;           // k*NN + i
    const int i = bid & (NN - 1);
    const float* Arow = A + (size_t)bid * NN;
    __half* AhRow = g_Ah + (size_t)bid * NN;
    const int t = threadIdx.x;

    float acc = 0.f;
    #pragma unroll
    for (int j = 0; j < 4; j++) {
        float4 v = *reinterpret_cast<const float4*>(Arow + (size_t)(t + 256 * j) * 4);
        acc += (v.x + v.y) + (v.z + v.w);
        uint2 w = make_uint2(f16x2(v.x, v.y), f16x2(v.z, v.w));
        *reinterpret_cast<uint2*>(AhRow + (size_t)(t + 256 * j) * 4) = w;
    }
    #pragma unroll
    for (int o = 16; o > 0; o >>= 1) acc += __shfl_down_sync(0xffffffffu, acc, o);
    if ((t & 31) == 0) wsum[t >> 5] = acc;
    __syncthreads();
    if (t < 64) {
        float p = g_E[(size_t)i * DD + t] * g_S[t];
        #pragma unroll
        for (int o = 16; o > 0; o >>= 1) p += __shfl_down_sync(0xffffffffu, p, o);
        if ((t & 31) == 0) dsum[t >> 5] = p;
    }
    __syncthreads();
    if (t == 0) {
        float rs = 0.f;
        #pragma unroll
        for (int w = 0; w < 8; w++) rs += wsum[w];
        float deg = rs + __ldg(alpha_p) * (dsum[0] + dsum[1]);
        g_dinv[bid] = 1.0f / sqrtf(deg);
    }
}

// ---------------- Yh[k][n][j] = fp16( dinv[k][j] * XW[k][j][n] ) ------------
__global__ void prep_kernel() {
    __shared__ float T[64][65];
    const int k = blockIdx.y;
    const int jb = blockIdx.x * 64;
    const int t = threadIdx.x;

    #pragma unroll
    for (int q = 0; q < 4; q++) {
        int idx = t + 256 * q;            // 1024 float4
        int r = idx >> 4;
        int c4 = idx & 15;
        float dv = g_dinv[(size_t)k * NN + jb + r];
        float4 v = *reinterpret_cast<const float4*>(g_XW + ((size_t)k * NN + jb + r) * DD + c4 * 4);
        T[r][c4 * 4 + 0] = v.x * dv;
        T[r][c4 * 4 + 1] = v.y * dv;
        T[r][c4 * 4 + 2] = v.z * dv;
        T[r][c4 * 4 + 3] = v.w * dv;
    }
    __syncthreads();

    const int n = t >> 2;
    const int jq = t & 3;
    const size_t base = ((size_t)k * DD + n) * NN + jb + jq * 16;
    uint32_t w[8];
    #pragma unroll
    for (int m4 = 0; m4 < 4; m4++) {
        w[2 * m4 + 0] = f16x2(T[jq * 16 + m4 * 4 + 0][n], T[jq * 16 + m4 * 4 + 1][n]);
        w[2 * m4 + 1] = f16x2(T[jq * 16 + m4 * 4 + 2][n], T[jq * 16 + m4 * 4 + 3][n]);
    }
    *reinterpret_cast<uint4*>(g_Yh + base)     = make_uint4(w[0], w[1], w[2], w[3]);
    *reinterpret_cast<uint4*>(g_Yh + base + 8) = make_uint4(w[4], w[5], w[6], w[7]);
}

// ---------------- M_k = E^T @ (d_k . XW_k)  (64x64 each) --------------------
__global__ void mmat_kernel() {
    __shared__ float Es[64][DD];
    __shared__ float Ys[64][DD];
    const int k = blockIdx.y;
    const int base = blockIdx.x * 64;
    const int t = threadIdx.x;

    #pragma unroll
    for (int i = 0; i < 4; i++) {
        int idx = t + 256 * i;
        int row = idx >> 4;
        int c4 = idx & 15;
        float4 e = *reinterpret_cast<const float4*>(g_E + (size_t)(base + row) * DD + c4 * 4);
        *reinterpret_cast<float4*>(&Es[row][c4 * 4]) = e;
        float dv = g_dinv[(size_t)k * NN + base + row];
        float4 xw = *reinterpret_cast<const float4*>(g_XW + ((size_t)k * NN + base + row) * DD + c4 * 4);
        xw.x *= dv; xw.y *= dv; xw.z *= dv; xw.w *= dv;
        *reinterpret_cast<float4*>(&Ys[row][c4 * 4]) = xw;
    }
    __syncthreads();

    const int t1 = t >> 4, t2 = t & 15;
    float acc[4][4] = {};
    for (int j = 0; j < 64; j++) {
        float4 e = *reinterpret_cast<const float4*>(&Es[j][t1 * 4]);
        float4 y = *reinterpret_cast<const float4*>(&Ys[j][t2 * 4]);
        float ea[4] = {e.x, e.y, e.z, e.w};
        float ya[4] = {y.x, y.y, y.z, y.w};
        #pragma unroll
        for (int a = 0; a < 4; a++)
            #pragma unroll
            for (int b = 0; b < 4; b++) acc[a][b] += ea[a] * ya[b];
    }
    #pragma unroll
    for (int a = 0; a < 4; a++)
        #pragma unroll
        for (int b = 0; b < 4; b++)
            atomicAdd(&g_M[(size_t)k * DD * DD + (t1 * 4 + a) * DD + t2 * 4 + b], acc[a][b]);
}

// ---------------- EM_k = alpha * E @ M_k  (4096x64 per hop) -----------------
// grid (64, KH), block 256.
__global__ void em_kernel(const float* __restrict__ alpha_p) {
    __shared__ float Ms[DD][DD];
    __shared__ float Es[64][DD];
    const int k = blockIdx.y;
    const int base = blockIdx.x * 64;
    const int t = threadIdx.x;

    #pragma unroll
    for (int q = 0; q < 16; q++) {
        int idx = t + 256 * q;
        Ms[idx >> 6][idx & 63] = g_M[(size_t)k * DD * DD + idx];
        Es[idx >> 6][idx & 63] = g_E[(size_t)(base + (idx >> 6)) * DD + (idx & 63)];
    }
    __syncthreads();

    const float alpha = __ldg(alpha_p);
    const int ti = t >> 6, c = t & 63;
    #pragma unroll 4
    for (int m = 0; m < 16; m++) {
        int row = ti + 4 * m;
        float dot = 0.f;
        #pragma unroll 8
        for (int c1 = 0; c1 < DD; c1++) dot += Es[row][c1] * Ms[c1][c];
        g_EM[((size_t)k * NN + base + row) * DD + c] = alpha * dot;
    }
}

// ---------------- C_k = A_k @ Y_k via mma.sync fp16 + ldmatrix --------------
// grid (32, KH, 3), block 256 (8 warps, warp tile 32x32). One full wave.
// K chunk 64. A/B smem rows of 64 fp16 (128B), XOR swizzle kg ^= (row&7) so
// every 8x8 LDSM tile reads 8 distinct 16B groups (conflict-free).
#define A_STAGE 16384                         // 128*64*2
#define B_STAGE 8192                          // 64*64*2
#define STAGE_BYTES (A_STAGE + B_STAGE)       // 24576
#define SPMM_SMEM (2 * STAGE_BYTES)           // 49152

__global__ void __launch_bounds__(256, 2) spmm_mma_kernel() {
    extern __shared__ char smem[];
    const uint32_t sb = smem_u32(smem);
    const int t = threadIdx.x;
    const int wid = t >> 5;
    const int lid = t & 31;
    const int g = lid >> 2;                // 0..7
    const int tig = lid & 3;               // 0..3
    const int warpM = wid >> 1;            // 0..3
    const int warpN = wid & 1;             // 0..1
    const int k = blockIdx.y;
    const int r0 = blockIdx.x * 128;
    const int kz = blockIdx.z;
    const int ch0 = (kz * NCHTOT) / SPLIT;
    const int ch1 = ((kz + 1) * NCHTOT) / SPLIT;
    const int nch = ch1 - ch0;             // 21/21/22
    const size_t k0 = (size_t)ch0 * KCHUNK;

    // ---- fill geometry (16B units, swizzled dst) ----
    uint32_t adst[4];
    const __half* asrc[4];
    #pragma unroll
    for (int q = 0; q < 4; q++) {
        int idx = t + 256 * q;             // 1024 units = 128 rows x 8 groups
        int row = idx >> 3;
        int kg = idx & 7;
        adst[q] = (uint32_t)(row * 128 + ((kg ^ (row & 7)) << 4));
        asrc[q] = g_Ah + ((size_t)k * NN + r0 + row) * NN + k0 + kg * 8;
    }
    uint32_t bdst[2];
    const __half* bsrc[2];
    #pragma unroll
    for (int q = 0; q < 2; q++) {
        int idx = t + 256 * q;             // 512 units = 64 rows x 8 groups
        int row = idx >> 3;
        int kg = idx & 7;
        bdst[q] = (uint32_t)(A_STAGE + row * 128 + ((kg ^ (row & 7)) << 4));
        bsrc[q] = g_Yh + ((size_t)k * DD + row) * NN + k0 + kg * 8;
    }

    // ---- ldmatrix per-lane geometry ----
    const int lj = lid & 7;                // row within 8x8 tile
    const int liq = lid >> 3;              // matrix index 0..3
    // A: m0=(rows+0,klo) m1=(rows+8,klo) m2=(rows+0,khi) m3=(rows+8,khi)
    const int a_row = warpM * 32 + (liq & 1) * 8 + lj;     // mt=0 row
    const int a_kgb = liq >> 1;
    const uint32_t a_off = (uint32_t)(a_row * 128);
    const int a_sw = a_row & 7;
    // B: m0=(n+0,klo) m1=(n+0,khi) m2=(n+8,klo) m3=(n+8,khi)
    const int b_n = warpN * 32 + (liq >> 1) * 8 + lj;      // np=0 n
    const int b_kgb = liq & 1;
    const uint32_t b_off = (uint32_t)(A_STAGE + b_n * 128);
    const int b_sw = b_n & 7;

    float acc[2][4][4];
    #pragma unroll
    for (int mt = 0; mt < 2; mt++)
        #pragma unroll
        for (int nt = 0; nt < 4; nt++)
            #pragma unroll
            for (int r = 0; r < 4; r++) acc[mt][nt][r] = 0.f;

    // issue chunk 0
    {
        #pragma unroll
        for (int q = 0; q < 4; q++) CP_ASYNC16(sb + adst[q], asrc[q]);
        #pragma unroll
        for (int q = 0; q < 2; q++) CP_ASYNC16(sb + bdst[q], bsrc[q]);
        CP_COMMIT();
    }

    for (int i = 0; i < nch; i++) {
        const int st = i & 1;
        if (i + 1 < nch) {
            const uint32_t soff = sb + ((i + 1) & 1) * STAGE_BYTES;
            const int kb = (i + 1) * KCHUNK;
            #pragma unroll
            for (int q = 0; q < 4; q++) CP_ASYNC16(soff + adst[q], asrc[q] + kb);
            #pragma unroll
            for (int q = 0; q < 2; q++) CP_ASYNC16(soff + bdst[q], bsrc[q] + kb);
            CP_COMMIT();
            CP_WAIT(1);
        } else {
            CP_WAIT(0);
        }
        __syncthreads();

        const uint32_t sAb = sb + st * STAGE_BYTES;

        #pragma unroll
        for (int kb16 = 0; kb16 < 4; kb16++) {
            uint32_t af[2][4], bq0[4], bq1[4];
            const int akg = kb16 * 2 + a_kgb;
            const uint32_t aa = sAb + a_off + (uint32_t)((akg ^ a_sw) << 4);
            LDSM_X4(af[0][0], af[0][1], af[0][2], af[0][3], aa);
            LDSM_X4(af[1][0], af[1][1], af[1][2], af[1][3], aa + 2048);
            const int bkg = kb16 * 2 + b_kgb;
            const uint32_t ba = sAb + b_off + (uint32_t)((bkg ^ b_sw) << 4);
            LDSM_X4(bq0[0], bq0[1], bq0[2], bq0[3], ba);
            LDSM_X4(bq1[0], bq1[1], bq1[2], bq1[3], ba + 2048);
            uint32_t bf[4][2] = {{bq0[0], bq0[1]}, {bq0[2], bq0[3]},
                                 {bq1[0], bq1[1]}, {bq1[2], bq1[3]}};
            #pragma unroll
            for (int mt = 0; mt < 2; mt++)
                #pragma unroll
                for (int nt = 0; nt < 4; nt++)
                    mma_f16(acc[mt][nt], af[mt], bf[nt]);
        }
        __syncthreads();
    }

    // ---- epilogue: write partial C ----
    float* Cb = g_Cp + ((size_t)kz * KH + k) * NN * DD + (size_t)r0 * DD;
    #pragma unroll
    for (int mt = 0; mt < 2; mt++) {
        const int row = warpM * 32 + mt * 16 + g;
        #pragma unroll
        for (int nt = 0; nt < 4; nt++) {
            const int col = warpN * 32 + nt * 8 + 2 * tig;
            *reinterpret_cast<float2*>(Cb + (size_t)row * DD + col) =
                make_float2(acc[mt][nt][0], acc[mt][nt][1]);
            *reinterpret_cast<float2*>(Cb + (size_t)(row + 8) * DD + col) =
                make_float2(acc[mt][nt][2], acc[mt][nt][3]);
        }
    }
}

// ---------------- out = relu( sum_k dinv_k[i] * (sum_z Cp + EM_k) ) ---------
// Pure streaming. grid 256, block 256, float4 per thread.
__global__ void final_kernel(float* __restrict__ out) {
    const int gid = blockIdx.x * 256 + threadIdx.x;
    const int i = gid >> 4;
    const int c = (gid & 15) * 4;

    float4 acc = make_float4(0.f, 0.f, 0.f, 0.f);
    #pragma unroll
    for (int k = 0; k < KH; k++) {
        const size_t idx = ((size_t)k * NN + i) * DD + c;
        float4 s = *reinterpret_cast<const float4*>(g_EM + idx);
        #pragma unroll
        for (int z = 0; z < SPLIT; z++) {
            float4 v = *reinterpret_cast<const float4*>(g_Cp + (size_t)z * (KH * NN * DD) + idx);
            s.x += v.x; s.y += v.y; s.z += v.z; s.w += v.w;
        }
        const float d = g_dinv[(size_t)k * NN + i];
        acc.x += d * s.x; acc.y += d * s.y; acc.z += d * s.z; acc.w += d * s.w;
    }
    float4 r = make_float4(fmaxf(acc.x, 0.f), fmaxf(acc.y, 0.f),
                           fmaxf(acc.z, 0.f), fmaxf(acc.w, 0.f));
    *reinterpret_cast<float4*>(out + (size_t)i * DD + c) = r;
}

// ---------------- launch ----------------------------------------------------
extern "C" void kernel_launch(void* const* d_in, const int* in_sizes, int n_in,
                              void* d_out, int out_size) {
    const float* X     = (const float*)d_in[0];
    const float* A     = (const float*)d_in[1];
    const float* Wemb  = (const float*)d_in[2];
    const float* Whops = (const float*)d_in[3];
    const float* alpha = (const float*)d_in[4];
    float* out = (float*)d_out;

    cudaFuncSetAttribute(spmm_mma_kernel,
                         cudaFuncAttributeMaxDynamicSharedMemorySize, SPMM_SMEM);

    zero_kernel<<<48, 256>>>();
    proj_kernel<<<dim3(256, 4), 256>>>(X, Wemb, Whops);
    colsum_kernel<<<32, 256>>>();
    deg_kernel<<<KH * NN, 256>>>(A, alpha);
    prep_kernel<<<dim3(64, KH), 256>>>();
    mmat_kernel<<<dim3(64, KH), 256>>>();
    em_kernel<<<dim3(64, KH), 256>>>(alpha);
    spmm_mma_kernel<<<dim3(32, KH, SPLIT), 256, SPMM_SMEM>>>();
    final_kernel<<<256, 256>>>(out);
}